// round 8
// baseline (speedup 1.0000x reference)
#include <cuda_runtime.h>
#include <math.h>

#define PS 16
#define NB 32
#define IH 1024
#define IW 1024
#define IMGSZ (IH*IW)
#define TROW 33                   // padded row stride within a batch slice
#define TBATCH (PS*TROW)          // 528 floats per batch slice
#define TILE_BYTES (NB*TBATCH*4)  // 67584 B dynamic smem

__device__ __forceinline__ float clamp01(float x) {
    return fminf(fmaxf(x, 0.0f), 1.0f);
}

// ---------------------------------------------------------------------------
// One CTA = one PATCH-PAIR (sy, 2k/2k+1), all 32 batches. 256 threads.
// Warp w covers row w (cols 0..31, dense 128 B); each thread also owns row
// w+8. Batch halves: half-1 (b 0..15) -> smem tile; half-2 (b 16..31) ->
// tile AND registers (kept live through stats so apply reads regs, not LDS).
// ---------------------------------------------------------------------------
__global__ void __launch_bounds__(256, 3)
fused_kernel(const float* __restrict__ img,
             const float* __restrict__ noise,
             const float* __restrict__ r_strong,
             const float* __restrict__ r_drop,
             const float* __restrict__ r_else,
             const float* __restrict__ bright_f,
             const float* __restrict__ contrast_f,
             const float* __restrict__ slight_f,
             const int*   __restrict__ aug_choice,
             const int*   __restrict__ slight_choice,
             float* __restrict__ out) {
    extern __shared__ float tile[];           // [NB][16][33]
    __shared__ float s_qual[2][NB];
    __shared__ float s_mean[2][NB];
    __shared__ int   s_code[2];
    __shared__ float s_alpha[2], s_beta[2], s_delta[2];

    const int bx   = blockIdx.x;              // 0..2047
    const int sy   = bx >> 5;                 // patch row 0..63
    const int pair = bx & 31;                 // pair index 0..31
    const int t    = threadIdx.x;
    const int w    = t >> 5;                  // warp = row 0..7
    const int c2   = t & 31;                  // col across pair

    const int g0 = (sy * PS + w) * IW + pair * 32 + c2;   // row w
    const int g1 = g0 + 8 * IW;                           // row w+8
    const int t0 = w * TROW + c2;
    const int t1 = (w + 8) * TROW + c2;

    // ---- Phase 1a: half-1 (b 0..15), 32 front-batched dense LDGs -> tile ----
    {
        float a0[16], a1[16];
#pragma unroll
        for (int k = 0; k < 16; ++k) {
            a0[k] = img[g0 + k * IMGSZ];
            a1[k] = img[g1 + k * IMGSZ];
        }
#pragma unroll
        for (int k = 0; k < 16; ++k) {
            tile[k * TBATCH + t0] = a0[k];
            tile[k * TBATCH + t1] = a1[k];
        }
    }
    // ---- Phase 1b: half-2 (b 16..31) -> tile AND registers ----
    float v0[16], v1[16];
#pragma unroll
    for (int k = 0; k < 16; ++k) {
        v0[k] = img[g0 + (k + 16) * IMGSZ];
        v1[k] = img[g1 + (k + 16) * IMGSZ];
    }
#pragma unroll
    for (int k = 0; k < 16; ++k) {
        tile[(k + 16) * TBATCH + t0] = v0[k];
        tile[(k + 16) * TBATCH + t1] = v1[k];
    }
    __syncthreads();

    // ---- Phase 2: per-(patch,b) stats. Group = 4 threads, 4 rows each ----
    {
        const int g     = t >> 2;             // 0..63
        const int patch = g >> 5;             // 0..1
        const int b     = g & 31;
        const int j     = t & 3;              // rows 4j..4j+3
        const float* trow = tile + b * TBATCH + (4 * j) * TROW + patch * PS;
        float s = 0.f, ss = 0.f;
#pragma unroll
        for (int k = 0; k < 4; ++k) {
#pragma unroll
            for (int cc = 0; cc < PS; ++cc) {
                float x = trow[k * TROW + cc];
                s  += x;
                ss  = fmaf(x, x, ss);
            }
        }
#pragma unroll
        for (int off = 2; off >= 1; off >>= 1) {
            s  += __shfl_down_sync(0xffffffffu, s,  off, 4);
            ss += __shfl_down_sync(0xffffffffu, ss, off, 4);
        }
        if (j == 0) {
            float mean = s * (1.0f / 256.0f);
            float var  = (ss - s * s * (1.0f / 256.0f)) * (1.0f / 255.0f); // ddof=1
            var = fmaxf(var, 0.0f);
            float std_ = sqrtf(var);
            float iq   = 1.0f - 2.0f * fabsf(mean - 0.5f);
            s_qual[patch][b] = (std_ + iq + var) * (1.0f / 3.0f);
            s_mean[patch][b] = mean;
        }
    }
    __syncthreads();

    // ---- Phase 3: per-patch batch reduce + code -> affine coefficients ----
    if (t < 2) {
        const int patch = t;
        const int pg    = sy * 64 + pair * 2 + patch;
        float q = 0.f, m = 0.f;
#pragma unroll
        for (int b = 0; b < NB; ++b) { q += s_qual[patch][b]; m += s_mean[patch][b]; }
        q *= (1.0f / NB);
        m *= (1.0f / NB);

        bool low    = q < 0.7f;
        bool strong = low  && (r_strong[pg] < 0.8f);
        bool drop   = low  && (q < 0.3f) && (r_drop[pg] < 0.1f);
        bool els    = !low && (r_else[pg] < 0.3f);

        int code = 0;
        if (strong) code = aug_choice[pg] + 1;      // 1..4
        if (els)    code = slight_choice[pg] + 5;   // 5..6
        if (drop)   code = 7;

        float alpha = 1.f, beta = 0.f, delta = 0.f;
        if      (code == 1) beta = 0.1f;
        else if (code == 3) alpha = bright_f[pg];
        else if (code == 4) { float cf = contrast_f[pg]; alpha = cf; delta = m * (1.0f - cf); }
        else if (code == 5) beta = 0.05f;
        else if (code == 6) alpha = slight_f[pg];
        else if (code == 7) alpha = 0.f;

        s_code[patch]  = code;
        s_alpha[patch] = alpha;
        s_beta[patch]  = beta;
        s_delta[patch] = delta;
    }
    __syncthreads();

    // ---- Phase 4: apply + dense streaming stores ----
    const int   patch = c2 >> 4;              // uniform per half-warp
    const int   lc    = c2 & 15;
    const int   code  = s_code[patch];
    const float alpha = s_alpha[patch];
    const float beta  = s_beta[patch];
    const float delta = s_delta[patch];

    if (code == 2) {
        // 3x3 zero-padded blur confined to the patch, from smem tile.
#pragma unroll 4
        for (int b = 0; b < NB; ++b) {
            const float* tb = tile + b * TBATCH;
            float sum0 = 0.f, sum1 = 0.f;
#pragma unroll
            for (int dx = -1; dx <= 1; ++dx) {
                const int cc = lc + dx;
                if (cc < 0 || cc >= PS) continue;
#pragma unroll
                for (int dy = -1; dy <= 1; ++dy) {
                    const int rr0 = w + dy;           // 0..7 (+/-1)
                    const int rr1 = w + 8 + dy;       // 8..15 (+/-1)
                    if (rr0 >= 0)  sum0 += tb[rr0 * TROW + c2 + dx];
                    if (rr1 < PS)  sum1 += tb[rr1 * TROW + c2 + dx];
                }
            }
            __stcs(&out[g0 + b * IMGSZ], sum0 * (1.0f / 9.0f));
            __stcs(&out[g1 + b * IMGSZ], sum1 * (1.0f / 9.0f));
        }
    } else if (beta != 0.0f) {
#pragma unroll
        for (int k = 0; k < 16; ++k) {        // half-1 from tile
            float x0 = tile[k * TBATCH + t0];
            float x1 = tile[k * TBATCH + t1];
            float n0 = noise[g0 + k * IMGSZ];
            float n1 = noise[g1 + k * IMGSZ];
            __stcs(&out[g0 + k * IMGSZ], clamp01(fmaf(beta, n0, x0)));
            __stcs(&out[g1 + k * IMGSZ], clamp01(fmaf(beta, n1, x1)));
        }
#pragma unroll
        for (int k = 0; k < 16; ++k) {        // half-2 from registers
            float n0 = noise[g0 + (k + 16) * IMGSZ];
            float n1 = noise[g1 + (k + 16) * IMGSZ];
            __stcs(&out[g0 + (k + 16) * IMGSZ], clamp01(fmaf(beta, n0, v0[k])));
            __stcs(&out[g1 + (k + 16) * IMGSZ], clamp01(fmaf(beta, n1, v1[k])));
        }
    } else {
#pragma unroll
        for (int k = 0; k < 16; ++k) {        // half-1 from tile
            float x0 = tile[k * TBATCH + t0];
            float x1 = tile[k * TBATCH + t1];
            __stcs(&out[g0 + k * IMGSZ], clamp01(fmaf(alpha, x0, delta)));
            __stcs(&out[g1 + k * IMGSZ], clamp01(fmaf(alpha, x1, delta)));
        }
#pragma unroll
        for (int k = 0; k < 16; ++k) {        // half-2 from registers
            __stcs(&out[g0 + (k + 16) * IMGSZ], clamp01(fmaf(alpha, v0[k], delta)));
            __stcs(&out[g1 + (k + 16) * IMGSZ], clamp01(fmaf(alpha, v1[k], delta)));
        }
    }
}

extern "C" void kernel_launch(void* const* d_in, const int* in_sizes, int n_in,
                              void* d_out, int out_size) {
    const float* img           = (const float*)d_in[0];
    const float* noise         = (const float*)d_in[1];
    const float* r_strong      = (const float*)d_in[2];
    const float* r_drop        = (const float*)d_in[3];
    const float* r_else        = (const float*)d_in[4];
    const float* bright_f      = (const float*)d_in[5];
    const float* contrast_f    = (const float*)d_in[6];
    const float* slight_f      = (const float*)d_in[7];
    const int*   aug_choice    = (const int*)d_in[8];
    const int*   slight_choice = (const int*)d_in[9];
    float* out = (float*)d_out;

    cudaFuncSetAttribute(fused_kernel,
                         cudaFuncAttributeMaxDynamicSharedMemorySize,
                         TILE_BYTES);

    fused_kernel<<<2048, 256, TILE_BYTES>>>(img, noise, r_strong, r_drop,
                                            r_else, bright_f, contrast_f,
                                            slight_f, aug_choice,
                                            slight_choice, out);
}